// round 14
// baseline (speedup 1.0000x reference)
#include <cuda_runtime.h>
#include <cstdint>

// Fixed shapes
#define N_PTS   65536
#define DIM     128
#define NSTG    4
#define KCB     2048
#define TPB     256               // 8 warps, each owns 16 rows (M-split)
#define NPC     128               // points per CTA
#define NBLK    (N_PTS / NPC)     // 512
#define TN      64                // codewords per tile
#define NTILE   (KCB / TN)        // 32
#define RSTRIDE 132               // fp32 residual row stride
#define BSTRIDE 68                // u32 (bf16x2) codeword row stride in smem
#define CAP     16                // candidate cap per point
#define MARGIN  0.5f              // half-distance units

typedef uint32_t u32;
typedef unsigned long long u64;

// Scratch (no cudaMalloc allowed)
__device__ float g_chalf[NSTG * KCB];          // 0.5 * ||C_k||^2 (exact fp32)
__device__ u32   g_cbh[NSTG * KCB * 64];       // bf16x2-packed codebook
__device__ float g_partial[NBLK];

// ---------------- helpers ----------------------------------------------------
__device__ __forceinline__ u32 smem_u32(const void* p) {
    u32 a;
    asm("{ .reg .u64 t; cvta.to.shared.u64 t, %1; cvt.u32.u64 %0, t; }"
        : "=r"(a) : "l"(p));
    return a;
}
__device__ __forceinline__ void cp_async16(void* smem_ptr, const void* gmem_ptr) {
    unsigned s = (unsigned)__cvta_generic_to_shared(smem_ptr);
    asm volatile("cp.async.cg.shared.global [%0], [%1], 16;" :: "r"(s), "l"(gmem_ptr));
}
__device__ __forceinline__ void cp_commit() { asm volatile("cp.async.commit_group;"); }
__device__ __forceinline__ void cp_wait1()  { asm volatile("cp.async.wait_group 1;"); }
__device__ __forceinline__ void cp_wait0()  { asm volatile("cp.async.wait_group 0;"); }

__device__ __forceinline__ u32 pack_bf(float lo, float hi) {
    u32 d;
    asm("cvt.rn.bf16x2.f32 %0, %1, %2;" : "=r"(d) : "f"(hi), "f"(lo));
    return d;
}

__device__ __forceinline__ void mma_bf16(float& c0, float& c1, float& c2, float& c3,
                                         u32 a0, u32 a1, u32 a2, u32 a3,
                                         u32 b0, u32 b1) {
    asm volatile(
        "mma.sync.aligned.m16n8k16.row.col.f32.bf16.bf16.f32 "
        "{%0,%1,%2,%3}, {%4,%5,%6,%7}, {%8,%9}, {%0,%1,%2,%3};"
        : "+f"(c0), "+f"(c1), "+f"(c2), "+f"(c3)
        : "r"(a0), "r"(a1), "r"(a2), "r"(a3), "r"(b0), "r"(b1));
}

// ldmatrix x4: 4 8x8 b16 matrices; lanes 8j..8j+7 supply row addrs of matrix j
__device__ __forceinline__ void ldsm_x4(u32& r0, u32& r1, u32& r2, u32& r3,
                                        u32 saddr) {
    asm volatile("ldmatrix.sync.aligned.m8n8.x4.shared.b16 {%0,%1,%2,%3}, [%4];"
                 : "=r"(r0), "=r"(r1), "=r"(r2), "=r"(r3) : "r"(saddr));
}

// bf16 bits of f rounded toward -inf
__device__ __forceinline__ u32 bf16_rd(float f) {
    u32 u = __float_as_uint(f);
    u32 b = u >> 16;
    if ((u & 0xFFFFu) && (u >> 31)) b++;
    return b & 0xFFFFu;
}

// order-preserving float->u32 key (ascending)
__device__ __forceinline__ u32 fkey(float f) {
    u32 u = __float_as_uint(f);
    return (u & 0x80000000u) ? ~u : (u | 0x80000000u);
}
__device__ __forceinline__ float funkey(u32 k) {
    u32 u = (k & 0x80000000u) ? (k & 0x7FFFFFFFu) : ~k;
    return __uint_as_float(u);
}

// ---------------------------------------------------------------------------
// Kernel 0: exact half norms + bf16x2-packed codebook (32 threads/codeword)
// ---------------------------------------------------------------------------
__global__ void rvq_prep_kernel(const float* __restrict__ cb) {
    int gt = blockIdx.x * blockDim.x + threadIdx.x;
    int c  = gt >> 5;                 // codeword
    int l  = gt & 31;                 // lane within codeword
    if (c >= NSTG * KCB) return;
    const float4 v = ((const float4*)(cb + (size_t)c * DIM))[l];
    float s = v.x * v.x + v.y * v.y + v.z * v.z + v.w * v.w;
    // warp-segment (32-lane) reduce: codeword occupies exactly one warp
#pragma unroll
    for (int off = 16; off > 0; off >>= 1)
        s += __shfl_xor_sync(0xffffffffu, s, off);
    u32* dst = g_cbh + (size_t)c * 64;
    dst[2 * l]     = pack_bf(v.x, v.y);
    dst[2 * l + 1] = pack_bf(v.z, v.w);
    if (l == 0) g_chalf[c] = 0.5f * s;
}

// ---------------------------------------------------------------------------
// Kernel 1: fused RVQ. 128 points, 8 warps; warp w owns rows [16w, 16w+16).
// bf16 MMA sweep (A frags in regs, B frags via double-buffered ldmatrix.x4)
// -> coarse mins + candidates; exact fp32 rescore -> argmin, loss, update.
// ---------------------------------------------------------------------------
__global__ void __launch_bounds__(TPB, 2)
rvq_main_kernel(const float* __restrict__ x,
                const float* __restrict__ cb,
                float* __restrict__ out) {
    extern __shared__ char smraw[];
    float* rsm   = (float*)smraw;                    // 128*132 fp32 residual master
    u32*   cbt   = (u32*)(rsm + NPC * RSTRIDE);      // 2 * 64*68 bf16x2 tiles
    float* hct   = (float*)(cbt + 2 * TN * BSTRIDE); // 2 * 64 half-norms
    u32*   ccnt  = (u32*)(hct + 2 * TN);             // 128 counters
    u32*   clist = ccnt + NPC;                       // 128 * CAP entries
    float* cmin  = (float*)(clist + NPC * CAP);      // 128 coarse mins
    u64*   best  = (u64*)(cmin + NPC);               // 128 packed (key,k)
    float* red   = (float*)(best + NPC);             // 256 reduction

    const int tid  = threadIdx.x;
    const int w    = tid >> 5;
    const int lane = tid & 31;
    const int g    = lane >> 2;
    const int t    = lane & 3;
    const int w16  = w * 16;         // this warp's row base
    const int pt0  = tid & (NPC - 1);
    const int half = tid >> 7;
    const unsigned FULL = 0xffffffffu;

    // ldmatrix per-lane row offset (bytes) within a 16-codeword n-tile pair
    const int matq = lane >> 3;
    const u32 rowpart = (u32)((((matq >> 1) * 8 + (lane & 7)) * (BSTRIDE * 4))
                              + (matq & 1) * 16);

    // ---- load x block into rsm ----
    {
        const float4* x4 = (const float4*)x;
        float4* rsm4 = (float4*)rsm;
#pragma unroll
        for (int jj = 0; jj < 16; jj++) {
            int row = jj * 8 + (tid >> 5);
            int c4  = tid & 31;
            rsm4[row * (RSTRIDE / 4) + c4] =
                __ldg(&x4[((size_t)blockIdx.x * NPC + row) * 32 + c4]);
        }
    }
    __syncthreads();

    float lossl = 0.f;
    int   idx_reg[NSTG];

    for (int s = 0; s < NSTG; s++) {
        const float* Cs  = cb + (size_t)s * KCB * DIM;
        const float* hcs = g_chalf + s * KCB;
        const u32*   Ch  = g_cbh + (size_t)s * KCB * 64;

        // init (ordered before first appends by the first in-loop barrier)
        if (tid < NPC) {
            ccnt[tid] = 0;
            best[tid] = 0xFFFFFFFFFFFFFFFFull;
        }

        // ---- A-fragments (bf16x2): rows w16+g and w16+g+8, 32 regs ----
        u32 areg[2][16];
#pragma unroll
        for (int r01 = 0; r01 < 2; r01++) {
            const float* rp = rsm + (w16 + g + r01 * 8) * RSTRIDE;
#pragma unroll
            for (int u = 0; u < 16; u++) {
                int j = t + 4 * u;
                float2 v = *(const float2*)(rp + 2 * j);
                areg[r01][u] = pack_bf(v.x, v.y);
            }
        }

        // ||r||^2 for this thread's point (pre-update residual), for the loss
        float rn_own = 0.f;
        if (half == 0) {
            const float4* rrow0 = (const float4*)(rsm + pt0 * RSTRIDE);
#pragma unroll
            for (int i = 0; i < 32; i++) {
                float4 rv = rrow0[i];
                rn_own = fmaf(rv.x, rv.x, rn_own);
                rn_own = fmaf(rv.y, rv.y, rn_own);
                rn_own = fmaf(rv.z, rv.z, rn_own);
                rn_own = fmaf(rv.w, rv.w, rn_own);
            }
        }

        float rowmin[2] = {3.402823466e38f, 3.402823466e38f};

        // prologue: tile 0 -> buffer 0 (1024 16B-chunks) + half-norms
        {
#pragma unroll
            for (int jj = 0; jj < 4; jj++) {
                int f = tid + TPB * jj;
                int cw = f >> 4, chx = f & 15;
                cp_async16(cbt + cw * BSTRIDE + chx * 4, Ch + (size_t)cw * 64 + chx * 4);
            }
            if (tid < 16) cp_async16(hct + tid * 4, hcs + tid * 4);
            cp_commit();
        }

        for (int ch = 0; ch < NTILE; ch++) {
            const int buf = ch & 1;
            if (ch + 1 < NTILE) {
                u32* dst = cbt + (buf ^ 1) * TN * BSTRIDE;
                const u32* src = Ch + (size_t)(ch + 1) * TN * 64;
#pragma unroll
                for (int jj = 0; jj < 4; jj++) {
                    int f = tid + TPB * jj;
                    int cw = f >> 4, chx = f & 15;
                    cp_async16(dst + cw * BSTRIDE + chx * 4, src + (size_t)cw * 64 + chx * 4);
                }
                if (tid < 16)
                    cp_async16(hct + (buf ^ 1) * TN + tid * 4,
                               hcs + (ch + 1) * TN + tid * 4);
                cp_commit();
                cp_wait1();
            } else {
                cp_wait0();
            }
            __syncthreads();

            const u32*   cbu = cbt + buf * TN * BSTRIDE;
            const float* hcb = hct + buf * TN;
            const u32 tb = smem_u32(cbu) + rowpart;

            float acc[8][4];
#pragma unroll
            for (int n = 0; n < 8; n++)
#pragma unroll
                for (int i = 0; i < 4; i++) acc[n][i] = 0.f;

            // software-pipelined B fragments: load q+1 while q's MMAs issue
            u32 bfa[16], bfb[16];
#pragma unroll
            for (int j = 0; j < 4; j++)
                ldsm_x4(bfa[4 * j], bfa[4 * j + 1], bfa[4 * j + 2], bfa[4 * j + 3],
                        tb + (u32)(j * 16 * BSTRIDE * 4));

#pragma unroll
            for (int q = 0; q < 8; q++) {           // k-steps of 16
                u32* bf  = (q & 1) ? bfb : bfa;
                u32* bfn = (q & 1) ? bfa : bfb;
                if (q < 7) {
#pragma unroll
                    for (int j = 0; j < 4; j++)
                        ldsm_x4(bfn[4 * j], bfn[4 * j + 1],
                                bfn[4 * j + 2], bfn[4 * j + 3],
                                tb + (u32)(j * 16 * BSTRIDE * 4 + (q + 1) * 32));
                }
#pragma unroll
                for (int j = 0; j < 4; j++) {
                    mma_bf16(acc[2 * j][0], acc[2 * j][1],
                             acc[2 * j][2], acc[2 * j][3],
                             areg[0][2 * q], areg[1][2 * q],
                             areg[0][2 * q + 1], areg[1][2 * q + 1],
                             bf[4 * j], bf[4 * j + 1]);
                    mma_bf16(acc[2 * j + 1][0], acc[2 * j + 1][1],
                             acc[2 * j + 1][2], acc[2 * j + 1][3],
                             areg[0][2 * q], areg[1][2 * q],
                             areg[0][2 * q + 1], areg[1][2 * q + 1],
                             bf[4 * j + 2], bf[4 * j + 3]);
                }
            }

            // epilogue: half-dists, running mins, margin appends
            const int kbase = ch * TN;
            float tmin[2] = {3.402823466e38f, 3.402823466e38f};
#pragma unroll
            for (int n = 0; n < 8; n++) {
                float h0 = hcb[n * 8 + 2 * t];
                float h1 = hcb[n * 8 + 2 * t + 1];
                float d0 = h0 - acc[n][0];
                float d1 = h1 - acc[n][1];
                float d2 = h0 - acc[n][2];
                float d3 = h1 - acc[n][3];
                acc[n][0] = d0; acc[n][1] = d1;
                acc[n][2] = d2; acc[n][3] = d3;
                tmin[0] = fminf(tmin[0], fminf(d0, d1));
                tmin[1] = fminf(tmin[1], fminf(d2, d3));
            }
#pragma unroll
            for (int sl = 0; sl < 2; sl++) {
                float v = fminf(rowmin[sl], tmin[sl]);
                v = fminf(v, __shfl_xor_sync(FULL, v, 1));
                v = fminf(v, __shfl_xor_sync(FULL, v, 2));
                rowmin[sl] = v;
            }
#pragma unroll
            for (int n = 0; n < 8; n++) {
#pragma unroll
                for (int i = 0; i < 4; i++) {
                    int sl = i >> 1;
                    float d = acc[n][i];
                    if (d < rowmin[sl] + MARGIN) {
                        int k  = kbase + n * 8 + 2 * t + (i & 1);
                        int pt = w16 + g + ((i >> 1) ? 8 : 0);
                        u32 pos = atomicAdd(&ccnt[pt], 1u);
                        if (pos < CAP)
                            clist[pt * CAP + pos] = (bf16_rd(d) << 16) | (u32)k;
                    }
                }
            }
            __syncthreads();
        }

        // publish coarse mins (each point owned by exactly one warp)
        if (t == 0) {
            cmin[w16 + g]     = rowmin[0];
            cmin[w16 + g + 8] = rowmin[1];
        }
        __syncthreads();

        // ---- exact fp32 rescore: 2 threads per point (candidate stripes) ----
        {
            const float4* rrow = (const float4*)(rsm + pt0 * RSTRIDE);
            float cm  = cmin[pt0];
            u32   cnt = ccnt[pt0];

            if (cnt <= CAP) {
                for (u32 e = (u32)half; e < cnt; e += 2) {
                    u32 ent = clist[pt0 * CAP + e];
                    float dcoarse = __uint_as_float((ent >> 16) << 16);
                    if (dcoarse > cm + MARGIN) continue;
                    int k = (int)(ent & 0xFFFFu);
                    const float4* crow = (const float4*)(Cs + (size_t)k * DIM);
                    float dot = 0.f;
#pragma unroll
                    for (int i = 0; i < 32; i++) {
                        float4 c = __ldg(&crow[i]);
                        float4 rv = rrow[i];
                        dot = fmaf(rv.x, c.x, dot);
                        dot = fmaf(rv.y, c.y, dot);
                        dot = fmaf(rv.z, c.z, dot);
                        dot = fmaf(rv.w, c.w, dot);
                    }
                    float dh = __ldg(&hcs[k]) - dot;
                    atomicMin(&best[pt0], ((u64)fkey(dh) << 32) | (u64)(u32)k);
                }
            } else if (half == 0) {
                // rare overflow fallback: exact full scan
                for (int k = 0; k < KCB; k++) {
                    const float4* crow = (const float4*)(Cs + (size_t)k * DIM);
                    float dot = 0.f;
#pragma unroll
                    for (int i = 0; i < 32; i++) {
                        float4 c = __ldg(&crow[i]);
                        float4 rv = rrow[i];
                        dot = fmaf(rv.x, c.x, dot);
                        dot = fmaf(rv.y, c.y, dot);
                        dot = fmaf(rv.z, c.z, dot);
                        dot = fmaf(rv.w, c.w, dot);
                    }
                    float dh = __ldg(&hcs[k]) - dot;
                    atomicMin(&best[pt0], ((u64)fkey(dh) << 32) | (u64)(u32)k);
                }
            }
        }
        __syncthreads();

        const u64 b = best[pt0];
        const int bestk = (int)(u32)(b & 0xFFFFFFFFull);

        if (half == 0) {
            float bestd = funkey((u32)(b >> 32));
            idx_reg[s] = bestk;
            lossl += rn_own + 2.f * bestd;
        }

        // residual update: r -= C[bestk], split across the two half-threads
        {
            float4* wrow = (float4*)(rsm + pt0 * RSTRIDE) + half * 16;
            const float4* crow = (const float4*)(Cs + (size_t)bestk * DIM) + half * 16;
#pragma unroll
            for (int i = 0; i < 16; i++) {
                float4 c = __ldg(&crow[i]);
                float4 rv = wrow[i];
                rv.x -= c.x; rv.y -= c.y; rv.z -= c.z; rv.w -= c.w;
                wrow[i] = rv;
            }
        }
        __syncthreads();
    }

    // ---- x_q = x - residual_final ----
    {
        const float4* x4 = (const float4*)x;
        float4* out4 = (float4*)out;
        const float4* rsm4 = (const float4*)rsm;
#pragma unroll
        for (int jj = 0; jj < 16; jj++) {
            int row = jj * 8 + (tid >> 5);
            int c4  = tid & 31;
            size_t gi = ((size_t)blockIdx.x * NPC + row) * 32 + c4;
            float4 xv = __ldg(&x4[gi]);
            float4 rv = rsm4[row * (RSTRIDE / 4) + c4];
            float4 o;
            o.x = xv.x - rv.x; o.y = xv.y - rv.y;
            o.z = xv.z - rv.z; o.w = xv.w - rv.w;
            out4[gi] = o;
        }
    }

    // indices: [N, S] floats after x_q and loss scalar
    if (half == 0) {
        int n = blockIdx.x * NPC + pt0;
#pragma unroll
        for (int s = 0; s < NSTG; s++)
            out[(size_t)N_PTS * DIM + 1 + (size_t)n * NSTG + s] = (float)idx_reg[s];
    }

    // deterministic loss partial (only half==0 threads contributed)
    red[tid] = lossl;
    __syncthreads();
#pragma unroll
    for (int off = TPB / 2; off > 0; off >>= 1) {
        if (tid < off) red[tid] += red[tid + off];
        __syncthreads();
    }
    if (tid == 0) g_partial[blockIdx.x] = red[0];
}

// ---------------------------------------------------------------------------
// Kernel 2: final loss = 1.25 * sum(min dist) / (S*N*D)
// ---------------------------------------------------------------------------
__global__ void rvq_loss_kernel(float* __restrict__ out) {
    __shared__ float red[NBLK];
    int t = threadIdx.x;
    red[t] = g_partial[t];
    __syncthreads();
#pragma unroll
    for (int off = NBLK / 2; off > 0; off >>= 1) {
        if (t < off) red[t] += red[t + off];
        __syncthreads();
    }
    if (t == 0) {
        float scale = 1.25f / ((float)NSTG * (float)N_PTS * (float)DIM);
        out[(size_t)N_PTS * DIM] = red[0] * scale;
    }
}

// ---------------------------------------------------------------------------
extern "C" void kernel_launch(void* const* d_in, const int* in_sizes, int n_in,
                              void* d_out, int out_size) {
    const float* x  = (const float*)d_in[0];   // [N, D]
    const float* cb = (const float*)d_in[1];   // [S, K, D]
    float* out = (float*)d_out;                // [N*D | 1 | N*S]

    const int smem_bytes =
        NPC * RSTRIDE * 4 +            // rsm           67584
        2 * TN * BSTRIDE * 4 +         // cbt           34816
        2 * TN * 4 +                   // hct             512
        NPC * 4 +                      // ccnt            512
        NPC * CAP * 4 +                // clist          8192
        NPC * 4 +                      // cmin            512
        NPC * 8 +                      // best           1024
        TPB * 4;                       // red            1024   => 114176

    cudaFuncSetAttribute(rvq_main_kernel,
                         cudaFuncAttributeMaxDynamicSharedMemorySize, smem_bytes);

    rvq_prep_kernel<<<(NSTG * KCB * 32 + 255) / 256, 256>>>(cb);
    rvq_main_kernel<<<NBLK, TPB, smem_bytes>>>(x, cb, out);
    rvq_loss_kernel<<<1, NBLK>>>(out);
}

// round 15
// speedup vs baseline: 1.0168x; 1.0168x over previous
#include <cuda_runtime.h>
#include <cstdint>

// Fixed shapes
#define N_PTS   65536
#define DIM     128
#define NSTG    4
#define KCB     2048
#define TPB     256               // 8 warps, each owns 16 rows (M-split)
#define NPC     128               // points per CTA
#define NBLK    (N_PTS / NPC)     // 512
#define TN      64                // codewords per tile
#define NTILE   (KCB / TN)        // 32
#define RSTRIDE 132               // fp32 residual row stride
#define BSTRIDE 68                // u32 (bf16x2) codeword row stride in smem
#define CAP     16                // candidate cap per point
#define MARGIN  0.5f              // half-distance units

typedef uint32_t u32;
typedef unsigned long long u64;

// Scratch (no cudaMalloc allowed)
__device__ float g_chalf[NSTG * KCB];          // 0.5 * ||C_k||^2 (exact fp32)
__device__ u32   g_cbh[NSTG * KCB * 64];       // bf16x2-packed codebook
__device__ float g_partial[NBLK];

// ---------------- helpers ----------------------------------------------------
__device__ __forceinline__ u32 smem_u32(const void* p) {
    u32 a;
    asm("{ .reg .u64 t; cvta.to.shared.u64 t, %1; cvt.u32.u64 %0, t; }"
        : "=r"(a) : "l"(p));
    return a;
}
__device__ __forceinline__ void cp_async16(void* smem_ptr, const void* gmem_ptr) {
    unsigned s = (unsigned)__cvta_generic_to_shared(smem_ptr);
    asm volatile("cp.async.cg.shared.global [%0], [%1], 16;" :: "r"(s), "l"(gmem_ptr));
}
__device__ __forceinline__ void cp_commit() { asm volatile("cp.async.commit_group;"); }
__device__ __forceinline__ void cp_wait1()  { asm volatile("cp.async.wait_group 1;"); }
__device__ __forceinline__ void cp_wait0()  { asm volatile("cp.async.wait_group 0;"); }

__device__ __forceinline__ u32 pack_bf(float lo, float hi) {
    u32 d;
    asm("cvt.rn.bf16x2.f32 %0, %1, %2;" : "=r"(d) : "f"(hi), "f"(lo));
    return d;
}

__device__ __forceinline__ void mma_bf16(float& c0, float& c1, float& c2, float& c3,
                                         u32 a0, u32 a1, u32 a2, u32 a3,
                                         u32 b0, u32 b1) {
    asm volatile(
        "mma.sync.aligned.m16n8k16.row.col.f32.bf16.bf16.f32 "
        "{%0,%1,%2,%3}, {%4,%5,%6,%7}, {%8,%9}, {%0,%1,%2,%3};"
        : "+f"(c0), "+f"(c1), "+f"(c2), "+f"(c3)
        : "r"(a0), "r"(a1), "r"(a2), "r"(a3), "r"(b0), "r"(b1));
}

// ldmatrix x4: 4 8x8 b16 matrices; lanes 8j..8j+7 supply row addrs of matrix j
__device__ __forceinline__ void ldsm_x4(u32& r0, u32& r1, u32& r2, u32& r3,
                                        u32 saddr) {
    asm volatile("ldmatrix.sync.aligned.m8n8.x4.shared.b16 {%0,%1,%2,%3}, [%4];"
                 : "=r"(r0), "=r"(r1), "=r"(r2), "=r"(r3) : "r"(saddr));
}

// bf16 bits of f rounded toward -inf
__device__ __forceinline__ u32 bf16_rd(float f) {
    u32 u = __float_as_uint(f);
    u32 b = u >> 16;
    if ((u & 0xFFFFu) && (u >> 31)) b++;
    return b & 0xFFFFu;
}

// order-preserving float->u32 key (ascending)
__device__ __forceinline__ u32 fkey(float f) {
    u32 u = __float_as_uint(f);
    return (u & 0x80000000u) ? ~u : (u | 0x80000000u);
}
__device__ __forceinline__ float funkey(u32 k) {
    u32 u = (k & 0x80000000u) ? (k & 0x7FFFFFFFu) : ~k;
    return __uint_as_float(u);
}

// ---------------------------------------------------------------------------
// Kernel 0: exact half norms + bf16x2-packed codebook (32 threads/codeword)
// ---------------------------------------------------------------------------
__global__ void rvq_prep_kernel(const float* __restrict__ cb) {
    int gt = blockIdx.x * blockDim.x + threadIdx.x;
    int c  = gt >> 5;                 // codeword
    int l  = gt & 31;                 // lane within codeword
    if (c >= NSTG * KCB) return;
    const float4 v = ((const float4*)(cb + (size_t)c * DIM))[l];
    float s = v.x * v.x + v.y * v.y + v.z * v.z + v.w * v.w;
#pragma unroll
    for (int off = 16; off > 0; off >>= 1)
        s += __shfl_xor_sync(0xffffffffu, s, off);
    u32* dst = g_cbh + (size_t)c * 64;
    dst[2 * l]     = pack_bf(v.x, v.y);
    dst[2 * l + 1] = pack_bf(v.z, v.w);
    if (l == 0) g_chalf[c] = 0.5f * s;
}

// ---------------------------------------------------------------------------
// Kernel 1: fused RVQ. 128 points, 8 warps; warp w owns rows [16w, 16w+16).
// bf16 MMA sweep (A frags in regs, B frags via ldmatrix.x4) -> coarse mins +
// candidates; exact fp32 rescore (2 threads/point) -> argmin, loss, update.
// ---------------------------------------------------------------------------
__global__ void __launch_bounds__(TPB, 2)
rvq_main_kernel(const float* __restrict__ x,
                const float* __restrict__ cb,
                float* __restrict__ out) {
    extern __shared__ char smraw[];
    float* rsm   = (float*)smraw;                    // 128*132 fp32 residual master
    u32*   cbt   = (u32*)(rsm + NPC * RSTRIDE);      // 2 * 64*68 bf16x2 tiles
    float* hct   = (float*)(cbt + 2 * TN * BSTRIDE); // 2 * 64 half-norms
    u32*   ccnt  = (u32*)(hct + 2 * TN);             // 128 counters
    u32*   clist = ccnt + NPC;                       // 128 * CAP entries
    float* cmin  = (float*)(clist + NPC * CAP);      // 128 coarse mins
    u64*   best  = (u64*)(cmin + NPC);               // 128 packed (key,k)
    float* red   = (float*)(best + NPC);             // 256 reduction

    const int tid  = threadIdx.x;
    const int w    = tid >> 5;
    const int lane = tid & 31;
    const int g    = lane >> 2;
    const int t    = lane & 3;
    const int w16  = w * 16;         // this warp's row base
    const int pt0  = tid & (NPC - 1);
    const int half = tid >> 7;
    const unsigned FULL = 0xffffffffu;

    // ldmatrix per-lane row offset (bytes) within a 16-codeword n-tile pair
    const int matq = lane >> 3;
    const u32 rowpart = (u32)((((matq >> 1) * 8 + (lane & 7)) * (BSTRIDE * 4))
                              + (matq & 1) * 16);

    // ---- load x block into rsm ----
    {
        const float4* x4 = (const float4*)x;
        float4* rsm4 = (float4*)rsm;
#pragma unroll
        for (int jj = 0; jj < 16; jj++) {
            int row = jj * 8 + (tid >> 5);
            int c4  = tid & 31;
            rsm4[row * (RSTRIDE / 4) + c4] =
                __ldg(&x4[((size_t)blockIdx.x * NPC + row) * 32 + c4]);
        }
    }
    __syncthreads();

    float lossl = 0.f;
    int   idx_reg[NSTG];

    for (int s = 0; s < NSTG; s++) {
        const float* Cs  = cb + (size_t)s * KCB * DIM;
        const float* hcs = g_chalf + s * KCB;
        const u32*   Ch  = g_cbh + (size_t)s * KCB * 64;

        // init (ordered before first appends by the first in-loop barrier)
        if (tid < NPC) {
            ccnt[tid] = 0;
            best[tid] = 0xFFFFFFFFFFFFFFFFull;
        }

        // ---- A-fragments (bf16x2): rows w16+g and w16+g+8, 32 regs ----
        u32 areg[2][16];
#pragma unroll
        for (int r01 = 0; r01 < 2; r01++) {
            const float* rp = rsm + (w16 + g + r01 * 8) * RSTRIDE;
#pragma unroll
            for (int u = 0; u < 16; u++) {
                int j = t + 4 * u;
                float2 v = *(const float2*)(rp + 2 * j);
                areg[r01][u] = pack_bf(v.x, v.y);
            }
        }

        // ||r||^2 for this thread's point (pre-update residual), for the loss
        float rn_own = 0.f;
        if (half == 0) {
            const float4* rrow0 = (const float4*)(rsm + pt0 * RSTRIDE);
#pragma unroll
            for (int i = 0; i < 32; i++) {
                float4 rv = rrow0[i];
                rn_own = fmaf(rv.x, rv.x, rn_own);
                rn_own = fmaf(rv.y, rv.y, rn_own);
                rn_own = fmaf(rv.z, rv.z, rn_own);
                rn_own = fmaf(rv.w, rv.w, rn_own);
            }
        }

        float rowmin[2] = {3.402823466e38f, 3.402823466e38f};

        // prologue: tile 0 -> buffer 0 (1024 16B-chunks) + half-norms
        {
#pragma unroll
            for (int jj = 0; jj < 4; jj++) {
                int f = tid + TPB * jj;
                int cw = f >> 4, chx = f & 15;
                cp_async16(cbt + cw * BSTRIDE + chx * 4, Ch + (size_t)cw * 64 + chx * 4);
            }
            if (tid < 16) cp_async16(hct + tid * 4, hcs + tid * 4);
            cp_commit();
        }

        for (int ch = 0; ch < NTILE; ch++) {
            const int buf = ch & 1;
            if (ch + 1 < NTILE) {
                u32* dst = cbt + (buf ^ 1) * TN * BSTRIDE;
                const u32* src = Ch + (size_t)(ch + 1) * TN * 64;
#pragma unroll
                for (int jj = 0; jj < 4; jj++) {
                    int f = tid + TPB * jj;
                    int cw = f >> 4, chx = f & 15;
                    cp_async16(dst + cw * BSTRIDE + chx * 4, src + (size_t)cw * 64 + chx * 4);
                }
                if (tid < 16)
                    cp_async16(hct + (buf ^ 1) * TN + tid * 4,
                               hcs + (ch + 1) * TN + tid * 4);
                cp_commit();
                cp_wait1();
            } else {
                cp_wait0();
            }
            __syncthreads();

            const u32*   cbu = cbt + buf * TN * BSTRIDE;
            const float* hcb = hct + buf * TN;
            const u32 tb = smem_u32(cbu) + rowpart;

            float acc[8][4];
#pragma unroll
            for (int n = 0; n < 8; n++)
#pragma unroll
                for (int i = 0; i < 4; i++) acc[n][i] = 0.f;

#pragma unroll
            for (int q = 0; q < 8; q++) {           // k-steps of 16
                u32 bf[16];
#pragma unroll
                for (int j = 0; j < 4; j++)         // n-tile pairs (2j, 2j+1)
                    ldsm_x4(bf[4 * j], bf[4 * j + 1], bf[4 * j + 2], bf[4 * j + 3],
                            tb + (u32)(j * 16 * BSTRIDE * 4 + q * 32));
#pragma unroll
                for (int j = 0; j < 4; j++) {
                    mma_bf16(acc[2 * j][0], acc[2 * j][1],
                             acc[2 * j][2], acc[2 * j][3],
                             areg[0][2 * q], areg[1][2 * q],
                             areg[0][2 * q + 1], areg[1][2 * q + 1],
                             bf[4 * j], bf[4 * j + 1]);
                    mma_bf16(acc[2 * j + 1][0], acc[2 * j + 1][1],
                             acc[2 * j + 1][2], acc[2 * j + 1][3],
                             areg[0][2 * q], areg[1][2 * q],
                             areg[0][2 * q + 1], areg[1][2 * q + 1],
                             bf[4 * j + 2], bf[4 * j + 3]);
                }
            }

            // epilogue: half-dists, running mins, margin appends
            const int kbase = ch * TN;
            float tmin[2] = {3.402823466e38f, 3.402823466e38f};
#pragma unroll
            for (int n = 0; n < 8; n++) {
                float h0 = hcb[n * 8 + 2 * t];
                float h1 = hcb[n * 8 + 2 * t + 1];
                float d0 = h0 - acc[n][0];
                float d1 = h1 - acc[n][1];
                float d2 = h0 - acc[n][2];
                float d3 = h1 - acc[n][3];
                acc[n][0] = d0; acc[n][1] = d1;
                acc[n][2] = d2; acc[n][3] = d3;
                tmin[0] = fminf(tmin[0], fminf(d0, d1));
                tmin[1] = fminf(tmin[1], fminf(d2, d3));
            }
#pragma unroll
            for (int sl = 0; sl < 2; sl++) {
                float v = fminf(rowmin[sl], tmin[sl]);
                v = fminf(v, __shfl_xor_sync(FULL, v, 1));
                v = fminf(v, __shfl_xor_sync(FULL, v, 2));
                rowmin[sl] = v;
            }
#pragma unroll
            for (int n = 0; n < 8; n++) {
#pragma unroll
                for (int i = 0; i < 4; i++) {
                    int sl = i >> 1;
                    float d = acc[n][i];
                    if (d < rowmin[sl] + MARGIN) {
                        int k  = kbase + n * 8 + 2 * t + (i & 1);
                        int pt = w16 + g + ((i >> 1) ? 8 : 0);
                        u32 pos = atomicAdd(&ccnt[pt], 1u);
                        if (pos < CAP)
                            clist[pt * CAP + pos] = (bf16_rd(d) << 16) | (u32)k;
                    }
                }
            }
            __syncthreads();
        }

        // publish coarse mins (each point owned by exactly one warp)
        if (t == 0) {
            cmin[w16 + g]     = rowmin[0];
            cmin[w16 + g + 8] = rowmin[1];
        }
        __syncthreads();

        // ---- exact fp32 rescore: 2 threads per point (candidate stripes) ----
        {
            const float4* rrow = (const float4*)(rsm + pt0 * RSTRIDE);
            float cm  = cmin[pt0];
            u32   cnt = ccnt[pt0];

            if (cnt <= CAP) {
                for (u32 e = (u32)half; e < cnt; e += 2) {
                    u32 ent = clist[pt0 * CAP + e];
                    float dcoarse = __uint_as_float((ent >> 16) << 16);
                    if (dcoarse > cm + MARGIN) continue;
                    int k = (int)(ent & 0xFFFFu);
                    const float4* crow = (const float4*)(Cs + (size_t)k * DIM);
                    float dot = 0.f;
#pragma unroll
                    for (int i = 0; i < 32; i++) {
                        float4 c = __ldg(&crow[i]);
                        float4 rv = rrow[i];
                        dot = fmaf(rv.x, c.x, dot);
                        dot = fmaf(rv.y, c.y, dot);
                        dot = fmaf(rv.z, c.z, dot);
                        dot = fmaf(rv.w, c.w, dot);
                    }
                    float dh = __ldg(&hcs[k]) - dot;
                    atomicMin(&best[pt0], ((u64)fkey(dh) << 32) | (u64)(u32)k);
                }
            } else if (half == 0) {
                // rare overflow fallback: exact full scan
                for (int k = 0; k < KCB; k++) {
                    const float4* crow = (const float4*)(Cs + (size_t)k * DIM);
                    float dot = 0.f;
#pragma unroll
                    for (int i = 0; i < 32; i++) {
                        float4 c = __ldg(&crow[i]);
                        float4 rv = rrow[i];
                        dot = fmaf(rv.x, c.x, dot);
                        dot = fmaf(rv.y, c.y, dot);
                        dot = fmaf(rv.z, c.z, dot);
                        dot = fmaf(rv.w, c.w, dot);
                    }
                    float dh = __ldg(&hcs[k]) - dot;
                    atomicMin(&best[pt0], ((u64)fkey(dh) << 32) | (u64)(u32)k);
                }
            }
        }
        __syncthreads();

        const u64 b = best[pt0];
        const int bestk = (int)(u32)(b & 0xFFFFFFFFull);

        if (half == 0) {
            float bestd = funkey((u32)(b >> 32));
            idx_reg[s] = bestk;
            lossl += rn_own + 2.f * bestd;
        }

        // residual update: r -= C[bestk], split across the two half-threads
        {
            float4* wrow = (float4*)(rsm + pt0 * RSTRIDE) + half * 16;
            const float4* crow = (const float4*)(Cs + (size_t)bestk * DIM) + half * 16;
#pragma unroll
            for (int i = 0; i < 16; i++) {
                float4 c = __ldg(&crow[i]);
                float4 rv = wrow[i];
                rv.x -= c.x; rv.y -= c.y; rv.z -= c.z; rv.w -= c.w;
                wrow[i] = rv;
            }
        }
        __syncthreads();
    }

    // ---- x_q = x - residual_final ----
    {
        const float4* x4 = (const float4*)x;
        float4* out4 = (float4*)out;
        const float4* rsm4 = (const float4*)rsm;
#pragma unroll
        for (int jj = 0; jj < 16; jj++) {
            int row = jj * 8 + (tid >> 5);
            int c4  = tid & 31;
            size_t gi = ((size_t)blockIdx.x * NPC + row) * 32 + c4;
            float4 xv = __ldg(&x4[gi]);
            float4 rv = rsm4[row * (RSTRIDE / 4) + c4];
            float4 o;
            o.x = xv.x - rv.x; o.y = xv.y - rv.y;
            o.z = xv.z - rv.z; o.w = xv.w - rv.w;
            out4[gi] = o;
        }
    }

    // indices: [N, S] floats after x_q and loss scalar
    if (half == 0) {
        int n = blockIdx.x * NPC + pt0;
#pragma unroll
        for (int s = 0; s < NSTG; s++)
            out[(size_t)N_PTS * DIM + 1 + (size_t)n * NSTG + s] = (float)idx_reg[s];
    }

    // deterministic loss partial (only half==0 threads contributed)
    red[tid] = lossl;
    __syncthreads();
#pragma unroll
    for (int off = TPB / 2; off > 0; off >>= 1) {
        if (tid < off) red[tid] += red[tid + off];
        __syncthreads();
    }
    if (tid == 0) g_partial[blockIdx.x] = red[0];
}

// ---------------------------------------------------------------------------
// Kernel 2: final loss = 1.25 * sum(min dist) / (S*N*D)
// ---------------------------------------------------------------------------
__global__ void rvq_loss_kernel(float* __restrict__ out) {
    __shared__ float red[NBLK];
    int t = threadIdx.x;
    red[t] = g_partial[t];
    __syncthreads();
#pragma unroll
    for (int off = NBLK / 2; off > 0; off >>= 1) {
        if (t < off) red[t] += red[t + off];
        __syncthreads();
    }
    if (t == 0) {
        float scale = 1.25f / ((float)NSTG * (float)N_PTS * (float)DIM);
        out[(size_t)N_PTS * DIM] = red[0] * scale;
    }
}

// ---------------------------------------------------------------------------
extern "C" void kernel_launch(void* const* d_in, const int* in_sizes, int n_in,
                              void* d_out, int out_size) {
    const float* x  = (const float*)d_in[0];   // [N, D]
    const float* cb = (const float*)d_in[1];   // [S, K, D]
    float* out = (float*)d_out;                // [N*D | 1 | N*S]

    const int smem_bytes =
        NPC * RSTRIDE * 4 +            // rsm           67584
        2 * TN * BSTRIDE * 4 +         // cbt           34816
        2 * TN * 4 +                   // hct             512
        NPC * 4 +                      // ccnt            512
        NPC * CAP * 4 +                // clist          8192
        NPC * 4 +                      // cmin            512
        NPC * 8 +                      // best           1024
        TPB * 4;                       // red            1024   => 114176

    cudaFuncSetAttribute(rvq_main_kernel,
                         cudaFuncAttributeMaxDynamicSharedMemorySize, smem_bytes);

    rvq_prep_kernel<<<(NSTG * KCB * 32 + 255) / 256, 256>>>(cb);
    rvq_main_kernel<<<NBLK, TPB, smem_bytes>>>(x, cb, out);
    rvq_loss_kernel<<<1, NBLK>>>(out);
}